// round 8
// baseline (speedup 1.0000x reference)
#include <cuda_runtime.h>
#include <cuda_fp16.h>
#include <cstdint>

// ConvexSampler R8: persistent grid (148x8 CTAs, grid-stride over 8-row tiles)
// + PDL overlap of the fp16-table convert, labels folded into convert kernel.
// Inputs (metadata order):
//   d_in[0] z         float32 [8192*768]
//   d_in[1] label_ids int32   [8192]
//   d_in[2] idx_i     int32   [32768]
//   d_in[3] idx_j     int32   [32768]
//   d_in[4] s         float32 [32768]
// Output (flattened tuple, float32):
//   [0 .. 40960*768)        z_out (first 8192 rows = z exact copy, next 32768 = convex)
//   [40960*768 .. +40960)   labels (first 8192 = label_ids as float, rest = 150)

#define BATCH        8192
#define FEAT_DIM     768
#define NUM_CONVEX   32768
#define TOTAL_ROWS   (BATCH + NUM_CONVEX)
#define F4_PER_ROW   (FEAT_DIM / 4)      // 192
#define CHUNKS       96                  // threads per row-slot
#define ROWS_PER_SLOT 4
#define SLOTS        2
#define ROWS_PER_BLK (ROWS_PER_SLOT * SLOTS)   // 8
#define N_TILES      (TOTAL_ROWS / ROWS_PER_BLK)  // 5120
#define NBLK         (148 * 8)                    // 1184 persistent CTAs
#define UNSEEN_F     150.0f

// fp16 copy of z (scratch; __device__ global per allocation rules)
__device__ __align__(16) __half zh_buf[(size_t)BATCH * FEAT_DIM];

// ---- kernel 1: z (f32) -> zh_buf (fp16, RN) + all label outputs ----
// Fires launch_dependents immediately so the main kernel's copy tiles can
// begin while conversion is still running.
__global__ void __launch_bounds__(256)
convert_kernel(const float4* __restrict__ z,
               const int*    __restrict__ label_ids,
               float*        __restrict__ out_labels) {
    asm volatile("griddepcontrol.launch_dependents;" ::: "memory");
    const int t = blockIdx.x * blockDim.x + threadIdx.x;  // 0 .. 786431
    float4 v0 = __ldg(&z[2 * t]);
    float4 v1 = __ldg(&z[2 * t + 1]);
    __half2 h0 = __floats2half2_rn(v0.x, v0.y);
    __half2 h1 = __floats2half2_rn(v0.z, v0.w);
    __half2 h2 = __floats2half2_rn(v1.x, v1.y);
    __half2 h3 = __floats2half2_rn(v1.z, v1.w);
    uint4 o;
    o.x = *reinterpret_cast<unsigned*>(&h0);
    o.y = *reinterpret_cast<unsigned*>(&h1);
    o.z = *reinterpret_cast<unsigned*>(&h2);
    o.w = *reinterpret_cast<unsigned*>(&h3);
    reinterpret_cast<uint4*>(zh_buf)[t] = o;

    if (t < TOTAL_ROWS) {
        out_labels[t] = (t < BATCH) ? (float)__ldg(&label_ids[t]) : UNSEEN_F;
    }
}

// ---- kernel 2: persistent fused copy + convex blend ----
__global__ void __launch_bounds__(SLOTS * CHUNKS, 8)
convex_main_kernel(const float4* __restrict__ z,
                   const int*    __restrict__ idx_i,
                   const int*    __restrict__ idx_j,
                   const float*  __restrict__ s,
                   float4*       __restrict__ out_rows) {
    const int slot = threadIdx.x / CHUNKS;        // 0..1
    const int c    = threadIdx.x % CHUNKS;        // 0..95
    const uint2* __restrict__ zh = (const uint2*)zh_buf;  // 4 halfs per uint2

    for (int t = blockIdx.x; t < N_TILES; t += NBLK) {
        const int row0  = t * ROWS_PER_BLK;
        const int rbase = row0 + slot * ROWS_PER_SLOT;

        if (row0 < BATCH) {
            // ---- copy tile: no table dependency; runs under convert ----
            float4 v[ROWS_PER_SLOT][2];
#pragma unroll
            for (int r = 0; r < ROWS_PER_SLOT; r++) {
                const long base = (long)(rbase + r) * F4_PER_ROW;
                v[r][0] = __ldg(&z[base + c]);
                v[r][1] = __ldg(&z[base + CHUNKS + c]);
            }
#pragma unroll
            for (int r = 0; r < ROWS_PER_SLOT; r++) {
                const long base = (long)(rbase + r) * F4_PER_ROW;
                __stcs(&out_rows[base + c], v[r][0]);
                __stcs(&out_rows[base + CHUNKS + c], v[r][1]);
            }
        } else {
            // ---- convex tile: table must be ready (idempotent wait) ----
            asm volatile("griddepcontrol.wait;" ::: "memory");

            float sw[ROWS_PER_SLOT];
            long  bi[ROWS_PER_SLOT], bj[ROWS_PER_SLOT];
#pragma unroll
            for (int r = 0; r < ROWS_PER_SLOT; r++) {
                const int ci = rbase + r - BATCH;
                sw[r] = __ldg(&s[ci]);
                bi[r] = (long)__ldg(&idx_i[ci]) * F4_PER_ROW;
                bj[r] = (long)__ldg(&idx_j[ci]) * F4_PER_ROW;
            }
            // 16 independent 8B gather loads in flight
            uint2 a0[ROWS_PER_SLOT], a1[ROWS_PER_SLOT];
            uint2 b0[ROWS_PER_SLOT], b1[ROWS_PER_SLOT];
#pragma unroll
            for (int r = 0; r < ROWS_PER_SLOT; r++) {
                a0[r] = __ldg(&zh[bi[r] + c]);
                a1[r] = __ldg(&zh[bi[r] + CHUNKS + c]);
                b0[r] = __ldg(&zh[bj[r] + c]);
                b1[r] = __ldg(&zh[bj[r] + CHUNKS + c]);
            }
#pragma unroll
            for (int r = 0; r < ROWS_PER_SLOT; r++) {
                const float w = sw[r], ow = 1.0f - sw[r];
                const long obase = (long)(rbase + r) * F4_PER_ROW;

                float2 fa0 = __half22float2(*reinterpret_cast<__half2*>(&a0[r].x));
                float2 fa1 = __half22float2(*reinterpret_cast<__half2*>(&a0[r].y));
                float2 fb0 = __half22float2(*reinterpret_cast<__half2*>(&b0[r].x));
                float2 fb1 = __half22float2(*reinterpret_cast<__half2*>(&b0[r].y));
                float4 o;
                o.x = fmaf(w, fa0.x, ow * fb0.x);
                o.y = fmaf(w, fa0.y, ow * fb0.y);
                o.z = fmaf(w, fa1.x, ow * fb1.x);
                o.w = fmaf(w, fa1.y, ow * fb1.y);
                __stcs(&out_rows[obase + c], o);

                fa0 = __half22float2(*reinterpret_cast<__half2*>(&a1[r].x));
                fa1 = __half22float2(*reinterpret_cast<__half2*>(&a1[r].y));
                fb0 = __half22float2(*reinterpret_cast<__half2*>(&b1[r].x));
                fb1 = __half22float2(*reinterpret_cast<__half2*>(&b1[r].y));
                o.x = fmaf(w, fa0.x, ow * fb0.x);
                o.y = fmaf(w, fa0.y, ow * fb0.y);
                o.z = fmaf(w, fa1.x, ow * fb1.x);
                o.w = fmaf(w, fa1.y, ow * fb1.y);
                __stcs(&out_rows[obase + CHUNKS + c], o);
            }
        }
    }
}

extern "C" void kernel_launch(void* const* d_in, const int* in_sizes, int n_in,
                              void* d_out, int out_size) {
    const float* z         = (const float*)d_in[0];
    const int*   label_ids = (const int*)  d_in[1];
    const int*   idx_i     = (const int*)  d_in[2];
    const int*   idx_j     = (const int*)  d_in[3];
    const float* s         = (const float*)d_in[4];

    float* out        = (float*)d_out;
    float* out_labels = out + (long)TOTAL_ROWS * FEAT_DIM;

    // 1) fp16 gather table + labels (triggers dependents at start)
    const int n_cvt = (BATCH * FEAT_DIM) / 8;   // 786432 threads
    convert_kernel<<<n_cvt / 256, 256, 0, 0>>>(
        (const float4*)z, label_ids, out_labels);

    // 2) persistent fused copy + blend with programmatic dependency
    {
        cudaLaunchConfig_t cfg = {};
        cfg.gridDim  = dim3(NBLK, 1, 1);            // 1184
        cfg.blockDim = dim3(SLOTS * CHUNKS, 1, 1);  // 192
        cfg.dynamicSmemBytes = 0;
        cfg.stream = 0;
        cudaLaunchAttribute attr[1];
        attr[0].id = cudaLaunchAttributeProgrammaticStreamSerialization;
        attr[0].val.programmaticStreamSerializationAllowed = 1;
        cfg.attrs = attr;
        cfg.numAttrs = 1;
        cudaLaunchKernelEx(&cfg, convex_main_kernel,
                           (const float4*)z, idx_i, idx_j, s, (float4*)out);
    }
}